// round 15
// baseline (speedup 1.0000x reference)
#include <cuda_runtime.h>
#include <cstdint>

// ============================================================================
// Problem constants
// ============================================================================
#define M_TOTAL   32768
#define N_TOTAL   1024
#define K_TOTAL   1024
#define THRESH    0.05f

// ---- per-CTA row split: mma 96, popc 96, dp4a 64  (x 128 m-tiles)
#define MT        128
#define A_MMA     96
#define A_POPC    96
#define A_DP      64
#define M_MMA_TOT   (MT * A_MMA)            // 12288
#define M_POPC_TOT  (MT * A_POPC)           // 12288
#define M_DP_TOT    (MT * A_DP)             // 8192
#define R_POPC0   M_MMA_TOT                 // 12288
#define R_DP0     (M_MMA_TOT + M_POPC_TOT)  // 24576

#define NWORDS    32

// ---- mma engine (threads 0-255): 96M x 128N, 3-stage cp.async
#define TILE_K    64
#define NUM_KC    (K_TOTAL / TILE_K)        // 16
#define STAGES    3
#define PITCH     80
#define MMA_STAGE ((A_MMA + 128) * PITCH)   // 17920
#define SM_MMA_BYTES (STAGES * MMA_STAGE)   // 53760

// ---- popc engine (threads 256-511): 96M x 128N, full K resident
#define PX_WD_BYTES (A_POPC * 8)            // 768 per word
#define SM_PX_OFF  SM_MMA_BYTES             // 32 wd x 768 = 24576
#define SM_PW_OFF  (SM_PX_OFF + 24576)      // 32 wd x 128 x 8 = 32768

// ---- dp4a engine (threads 512-639): 64M x 128N, 2-stage, pitch 72
#define DP_PITCH  72
#define DP_A_BYTES (A_DP * DP_PITCH)        // 4608
#define DP_B_BYTES (128 * DP_PITCH)         // 9216
#define DP_STAGE  (DP_A_BYTES + DP_B_BYTES) // 13824
#define SM_DP_OFF  (SM_PW_OFF + 32768)      // 111104
#define SMEM_TOTAL (SM_DP_OFF + 2 * DP_STAGE) // 138752

#define N_TILES   8
#define TOTAL_CTAS (MT * N_TILES)           // 1024
#define THREADS   640

// ============================================================================
// Scratch (device globals — no runtime allocation)
// ============================================================================
__device__ int8_t g_xq[(size_t)M_TOTAL * K_TOTAL];    // 32 MiB (mma+dp ranges used)
__device__ int8_t g_wq[(size_t)N_TOTAL * K_TOTAL];    // 1 MiB
__device__ uint2  g_xpk[(size_t)NWORDS * M_POPC_TOT]; // 3 MiB [wd][r]
__device__ uint2  g_wpk[(size_t)NWORDS * N_TOTAL];    // 256 KiB [wd][c]

// ============================================================================
// Helpers
// ============================================================================
__device__ __forceinline__ uint32_t smem_u32(const void* p) {
    uint32_t a;
    asm("{ .reg .u64 t; cvta.to.shared.u64 t, %1; cvt.u32.u64 %0, t; }"
        : "=r"(a) : "l"(p));
    return a;
}

#define CP_ASYNC16(dst_u32, gsrc) \
    asm volatile("cp.async.cg.shared.global [%0], [%1], 16;" \
                 :: "r"(dst_u32), "l"(gsrc) : "memory")
#define CP_ASYNC8(dst_u32, gsrc) \
    asm volatile("cp.async.ca.shared.global [%0], [%1], 8;" \
                 :: "r"(dst_u32), "l"(gsrc) : "memory")
#define CP_ASYNC_COMMIT() asm volatile("cp.async.commit_group;" ::: "memory")
#define CP_ASYNC_WAIT(n)  asm volatile("cp.async.wait_group %0;" :: "n"(n) : "memory")
#define BAR(id, cnt) asm volatile("bar.sync %0, %1;" :: "n"(id), "n"(cnt) : "memory")

__device__ __forceinline__ void mma_s8(int* c, const uint32_t* a, const uint32_t* b) {
    asm volatile(
        "mma.sync.aligned.m16n8k32.row.col.s32.s8.s8.s32 "
        "{%0,%1,%2,%3}, {%4,%5,%6,%7}, {%8,%9}, {%0,%1,%2,%3};"
        : "+r"(c[0]), "+r"(c[1]), "+r"(c[2]), "+r"(c[3])
        : "r"(a[0]), "r"(a[1]), "r"(a[2]), "r"(a[3]), "r"(b[0]), "r"(b[1]));
}

__device__ __forceinline__ void ldsm_x4(uint32_t* r, uint32_t addr) {
    asm volatile("ldmatrix.sync.aligned.m8n8.x4.shared.b16 {%0,%1,%2,%3}, [%4];"
        : "=r"(r[0]), "=r"(r[1]), "=r"(r[2]), "=r"(r[3]) : "r"(addr));
}

__device__ __forceinline__ int8_t tq(float v) {
    return (fabsf(v) < THRESH) ? (int8_t)0 : (v > 0.f ? (int8_t)1 : (int8_t)-1);
}

// ============================================================================
// Prep (ONE kernel, each x row touched exactly once):
//   int8 quantize: x rows [0,12288) + [24576,32768) + all w
//   bit-pack:      x rows [12288,24576) + all w
// ============================================================================
#define N16_A (M_MMA_TOT * (K_TOTAL / 16))   // 786432
#define N16_D (M_DP_TOT * (K_TOTAL / 16))    // 524288
#define N16_W ((N_TOTAL * K_TOTAL) / 16)     // 65536
#define PK_X  (M_POPC_TOT * NWORDS)          // 393216
#define PK_W  (N_TOTAL * NWORDS)             // 32768
#define PREP_TOTAL (N16_A + N16_D + N16_W + PK_X + PK_W)

__global__ __launch_bounds__(256) void prep_kernel(
    const float* __restrict__ x, const float* __restrict__ w)
{
    int i = blockIdx.x * blockDim.x + threadIdx.x;
    if (i >= PREP_TOTAL) return;

    if (i < N16_A + N16_D + N16_W) {
        // ---- int8 quantize, 16 elems/thread
        const float4* src;
        int4* dst;
        if (i < N16_A) {
            src = (const float4*)x + i * 4;
            dst = (int4*)g_xq + i;
        } else if (i < N16_A + N16_D) {
            size_t idx16 = (size_t)R_DP0 * (K_TOTAL / 16) + (i - N16_A);
            src = (const float4*)x + idx16 * 4;
            dst = (int4*)g_xq + idx16;
        } else {
            int j = i - N16_A - N16_D;
            src = (const float4*)w + (size_t)j * 4;
            dst = (int4*)g_wq + j;
        }
        int8_t r[16];
        #pragma unroll
        for (int j = 0; j < 4; j++) {
            float4 v = src[j];
            r[j * 4 + 0] = tq(v.x); r[j * 4 + 1] = tq(v.y);
            r[j * 4 + 2] = tq(v.z); r[j * 4 + 3] = tq(v.w);
        }
        *dst = *reinterpret_cast<int4*>(r);
    } else {
        // ---- bit-pack 32 floats -> (e,n) masks
        int t = i - (N16_A + N16_D + N16_W);
        const float4* p;
        uint2* dst;
        if (t < PK_X) {
            int r = t % M_POPC_TOT, wd = t / M_POPC_TOT;
            p = (const float4*)(x + (size_t)(R_POPC0 + r) * K_TOTAL + wd * 32);
            dst = g_xpk + (size_t)wd * M_POPC_TOT + r;
        } else {
            int j = t - PK_X;
            int c = j & (N_TOTAL - 1), wd = j >> 10;
            p = (const float4*)(w + (size_t)c * K_TOTAL + wd * 32);
            dst = g_wpk + (size_t)wd * N_TOTAL + c;
        }
        uint32_t e = 0, n = 0;
        #pragma unroll
        for (int j = 0; j < 8; j++) {
            float4 v = p[j];
            float f[4] = {v.x, v.y, v.z, v.w};
            #pragma unroll
            for (int q = 0; q < 4; q++) {
                uint32_t nz = (fabsf(f[q]) >= THRESH) ? 1u : 0u;
                uint32_t ng = (nz && f[q] < 0.f) ? 1u : 0u;
                e |= nz << (j * 4 + q);
                n |= ng << (j * 4 + q);
            }
        }
        *dst = make_uint2(e, n);
    }
}

// ============================================================================
// Fused GEMM: 640 threads. Per SMSP: 2 mma + 2 popc + 1 dp4a warps.
//   tid 0-255  : mma.sync (tensor pipe)  rows [0, 12288)
//   tid 256-511: popcount (popc pipe)    rows [12288, 24576)
//   tid 512-639: dp4a     (fma pipe)     rows [24576, 32768)
// Engines fully decoupled (separate named barriers, separate SMEM).
// ============================================================================
__global__ __launch_bounds__(THREADS, 1) void ternary_gemm_kernel(float* __restrict__ out)
{
    extern __shared__ char smem[];
    const int tid = threadIdx.x;
    const int c = (int)blockIdx.x;
    const int n0 = (c & 7) * 128;
    const int mt = c >> 3;                 // 0..127
    const uint32_t sbase = smem_u32(smem);

    if (tid < 256) {
        // ===================== MMA ENGINE (96x128) — R14 proven ===========
        const int lane = tid & 31;
        const int wid  = tid >> 5;
        const int wn   = wid & 3;          // 4 n-cols of 32
        const int wm   = wid >> 2;         // 2 m-rows of 48
        const int m0   = mt * A_MMA;

        const uint64_t xg = __cvta_generic_to_global(g_xq);
        const uint64_t wg = __cvta_generic_to_global(g_wq);

        const int g8 = lane >> 3, t8 = lane & 7;
        const uint32_t a_lane = (uint32_t)((t8 + ((g8 & 1) << 3)) * PITCH + ((g8 >> 1) << 4));
        const uint32_t b_lane = (uint32_t)((t8 + ((g8 >> 1) << 3)) * PITCH + ((g8 & 1) << 4));

        auto load_stage = [&](int kc, int s) {
            uint32_t sb = sbase + s * MMA_STAGE;
            #pragma unroll
            for (int t = 0; t < 4; t++) {          // 896 chunks of 16B
                int i = tid + t * 256;
                if (i < 384) {                     // A: 96 rows x 4 seg
                    int row = i >> 2, seg = i & 3;
                    uint64_t src = xg + (uint64_t)(m0 + row) * K_TOTAL + kc * TILE_K + seg * 16;
                    CP_ASYNC16(sb + row * PITCH + seg * 16, src);
                } else if (i < 896) {              // B: 128 rows x 4 seg
                    int j = i - 384;
                    int row = j >> 2, seg = j & 3;
                    uint64_t src = wg + (uint64_t)(n0 + row) * K_TOTAL + kc * TILE_K + seg * 16;
                    CP_ASYNC16(sb + (A_MMA + row) * PITCH + seg * 16, src);
                }
            }
            CP_ASYNC_COMMIT();
        };

        int acc[3][4][4];
        #pragma unroll
        for (int mi = 0; mi < 3; mi++)
            #pragma unroll
            for (int ni = 0; ni < 4; ni++)
                #pragma unroll
                for (int q = 0; q < 4; q++) acc[mi][ni][q] = 0;

        load_stage(0, 0);
        load_stage(1, 1);

        for (int kc = 0; kc < NUM_KC; kc++) {
            if (kc + STAGES - 1 < NUM_KC) CP_ASYNC_WAIT(STAGES - 2);
            else                          CP_ASYNC_WAIT(0);
            BAR(1, 256);

            const uint32_t stage = sbase + (kc % STAGES) * MMA_STAGE;
            const uint32_t sa  = stage + (uint32_t)(wm * 48) * PITCH + a_lane;
            const uint32_t sbB = stage + (uint32_t)(A_MMA + wn * 32) * PITCH + b_lane;

            #pragma unroll
            for (int kk = 0; kk < 2; kk++) {
                const uint32_t ko = (uint32_t)(kk * 32);
                uint32_t a[3][4];
                #pragma unroll
                for (int mi = 0; mi < 3; mi++)
                    ldsm_x4(a[mi], sa + (uint32_t)(mi * 16) * PITCH + ko);
                uint32_t b[2][4];
                #pragma unroll
                for (int p = 0; p < 2; p++)
                    ldsm_x4(b[p], sbB + (uint32_t)(p * 16) * PITCH + ko);
                #pragma unroll
                for (int mi = 0; mi < 3; mi++)
                    #pragma unroll
                    for (int ni = 0; ni < 4; ni++)
                        mma_s8(acc[mi][ni], a[mi], &b[ni >> 1][(ni & 1) * 2]);
            }
            BAR(1, 256);

            if (kc + STAGES - 1 < NUM_KC)
                load_stage(kc + STAGES - 1, (kc + STAGES - 1) % STAGES);
        }

        #pragma unroll
        for (int mi = 0; mi < 3; mi++) {
            const int r = m0 + wm * 48 + mi * 16 + (lane >> 2);
            #pragma unroll
            for (int ni = 0; ni < 4; ni++) {
                const int cc = n0 + wn * 32 + ni * 8 + (lane & 3) * 2;
                float2 v0 = make_float2((float)acc[mi][ni][0], (float)acc[mi][ni][1]);
                float2 v1 = make_float2((float)acc[mi][ni][2], (float)acc[mi][ni][3]);
                *(float2*)(out + (size_t)r * N_TOTAL + cc)       = v0;
                *(float2*)(out + (size_t)(r + 8) * N_TOTAL + cc) = v1;
            }
        }
    } else if (tid < 512) {
        // ===================== POPC ENGINE (96x128) =======================
        const int ptid = tid - 256;        // 0..255
        const int tx = ptid & 15;          // col = tx + 16j
        const int ty = ptid >> 4;          // 0..15, rows ty*6..+5
        const int r0 = mt * A_POPC;

        const uint64_t xg = __cvta_generic_to_global(g_xpk);
        const uint64_t wg = __cvta_generic_to_global(g_wpk);
        const uint32_t px = sbase + SM_PX_OFF;   // [wd][96 rows] uint2
        const uint32_t pw = sbase + SM_PW_OFF;   // [wd][128 cols] uint2

        #pragma unroll
        for (int t = 0; t < 6; t++) {            // x: 1536 x 16B (2 rows/chunk)
            int i = ptid + t * 256;
            int wd = i / 48, off = i % 48;
            uint64_t src = xg + ((uint64_t)wd * M_POPC_TOT + r0 + off * 2) * 8;
            CP_ASYNC16(px + wd * PX_WD_BYTES + off * 16, src);
        }
        #pragma unroll
        for (int t = 0; t < 8; t++) {            // w: 2048 x 16B
            int i = ptid + t * 256;
            int wd = i >> 6, off = i & 63;
            uint64_t src = wg + ((uint64_t)wd * N_TOTAL + n0 + off * 2) * 8;
            CP_ASYNC16(pw + wd * 1024 + off * 16, src);
        }
        CP_ASYNC_COMMIT();
        CP_ASYNC_WAIT(0);
        BAR(2, 256);

        int acc[6][8];
        #pragma unroll
        for (int i = 0; i < 6; i++)
            #pragma unroll
            for (int j = 0; j < 8; j++) acc[i][j] = 0;

        const char* xb = smem + SM_PX_OFF + ty * 48;   // 6 rows x 8B
        const char* wb = smem + SM_PW_OFF + tx * 8;    // cols tx + 16j

        #pragma unroll 2
        for (int wd = 0; wd < NWORDS; wd++) {
            uint2 xr[6];
            #pragma unroll
            for (int q = 0; q < 6; q++)
                xr[q] = *(const uint2*)(xb + wd * PX_WD_BYTES + q * 8);
            #pragma unroll
            for (int j = 0; j < 8; j++) {
                uint2 wcv = *(const uint2*)(wb + wd * 1024 + j * 128);
                #pragma unroll
                for (int i = 0; i < 6; i++) {
                    uint32_t t = xr[i].x & wcv.x;
                    uint32_t d = t & (xr[i].y ^ wcv.y);
                    acc[i][j] += __popc(t) - 2 * __popc(d);
                }
            }
        }

        #pragma unroll
        for (int i = 0; i < 6; i++) {
            const int r = R_POPC0 + r0 + ty * 6 + i;
            float* prow = out + (size_t)r * N_TOTAL + n0 + tx;
            #pragma unroll
            for (int j = 0; j < 8; j++)
                prow[j * 16] = (float)acc[i][j];
        }
    } else {
        // ===================== DP4A ENGINE (64x128) =======================
        const int dtid = tid - 512;        // 0..127
        const int tx = dtid & 15;          // col = tx + 16j
        const int ty = dtid >> 4;          // 0..7, rows ty*8..+7
        const int m0 = R_DP0 + mt * A_DP;

        const uint64_t xg = __cvta_generic_to_global(g_xq);
        const uint64_t wg = __cvta_generic_to_global(g_wq);
        const uint32_t dbase = sbase + SM_DP_OFF;

        auto load_dp = [&](int kc, int s) {
            uint32_t sa = dbase + s * DP_STAGE;
            uint32_t sb = sa + DP_A_BYTES;
            #pragma unroll
            for (int t = 0; t < 12; t++) {         // 1536 chunks of 8B
                int i = dtid + t * 128;
                if (i < 512) {                     // A: 64 rows x 8 seg
                    int row = i >> 3, seg = i & 7;
                    uint64_t src = xg + (uint64_t)(m0 + row) * K_TOTAL + kc * 64 + seg * 8;
                    CP_ASYNC8(sa + row * DP_PITCH + seg * 8, src);
                } else {                           // B: 128 cols x 8 seg
                    int j = i - 512;
                    int col = j >> 3, seg = j & 7;
                    uint64_t src = wg + (uint64_t)(n0 + col) * K_TOTAL + kc * 64 + seg * 8;
                    CP_ASYNC8(sb + col * DP_PITCH + seg * 8, src);
                }
            }
            CP_ASYNC_COMMIT();
        };

        int acc[8][8];
        #pragma unroll
        for (int i = 0; i < 8; i++)
            #pragma unroll
            for (int j = 0; j < 8; j++) acc[i][j] = 0;

        load_dp(0, 0);

        #pragma unroll 1
        for (int kc = 0; kc < NUM_KC; kc++) {
            const int s = kc & 1;
            if (kc + 1 < NUM_KC) { load_dp(kc + 1, s ^ 1); CP_ASYNC_WAIT(1); }
            else                 { CP_ASYNC_WAIT(0); }
            BAR(3, 128);

            const char* aS = smem + SM_DP_OFF + s * DP_STAGE + (ty * 8) * DP_PITCH;
            const char* bS = smem + SM_DP_OFF + s * DP_STAGE + DP_A_BYTES + tx * DP_PITCH;

            #pragma unroll 2
            for (int g = 0; g < 8; g++) {          // 8B K-groups
                int2 aa[8];
                #pragma unroll
                for (int i = 0; i < 8; i++)
                    aa[i] = *(const int2*)(aS + i * DP_PITCH + g * 8);
                #pragma unroll
                for (int j = 0; j < 8; j++) {
                    int2 bb = *(const int2*)(bS + j * (16 * DP_PITCH) + g * 8);
                    #pragma unroll
                    for (int i = 0; i < 8; i++) {
                        int sum = acc[i][j];
                        sum = __dp4a(aa[i].x, bb.x, sum);
                        sum = __dp4a(aa[i].y, bb.y, sum);
                        acc[i][j] = sum;
                    }
                }
            }
            BAR(3, 128);
        }

        #pragma unroll
        for (int i = 0; i < 8; i++) {
            const int r = m0 + ty * 8 + i;
            float* prow = out + (size_t)r * N_TOTAL + n0 + tx;
            #pragma unroll
            for (int j = 0; j < 8; j++)
                prow[j * 16] = (float)acc[i][j];
        }
    }
}

// ============================================================================
// Launch (2 launches per call -> GEMM lands in the ncu profile slot)
// ============================================================================
extern "C" void kernel_launch(void* const* d_in, const int* in_sizes, int n_in,
                              void* d_out, int out_size)
{
    const float* x = (const float*)d_in[0];
    const float* w = (const float*)d_in[1];
    float* out = (float*)d_out;

    prep_kernel<<<(PREP_TOTAL + 255) / 256, 256>>>(x, w);

    static bool attr_set = false;
    if (!attr_set) {
        cudaFuncSetAttribute(ternary_gemm_kernel,
                             cudaFuncAttributeMaxDynamicSharedMemorySize, SMEM_TOTAL);
        attr_set = true;
    }
    ternary_gemm_kernel<<<TOTAL_CTAS, THREADS, SMEM_TOTAL>>>(out);
}

// round 16
// speedup vs baseline: 1.1091x; 1.1091x over previous
#include <cuda_runtime.h>
#include <cstdint>

// ============================================================================
// Problem constants
// ============================================================================
#define M_TOTAL   32768
#define N_TOTAL   1024
#define K_TOTAL   1024
#define THRESH    0.05f

// ---- per-CTA row split: mma 96, popc 112, dp4a 48  (x 128 m-tiles)
#define MT        128
#define A_MMA     96
#define A_POPC    112
#define A_DP      48
#define M_MMA_TOT   (MT * A_MMA)            // 12288
#define M_POPC_TOT  (MT * A_POPC)           // 14336
#define M_DP_TOT    (MT * A_DP)             // 6144
#define R_POPC0   M_MMA_TOT                 // 12288
#define R_DP0     (M_MMA_TOT + M_POPC_TOT)  // 26624

#define NWORDS    32

// ---- mma engine (threads 0-255): 96M x 128N, 3-stage cp.async
#define TILE_K    64
#define NUM_KC    (K_TOTAL / TILE_K)        // 16
#define STAGES    3
#define PITCH     80
#define MMA_STAGE ((A_MMA + 128) * PITCH)   // 17920
#define SM_MMA_BYTES (STAGES * MMA_STAGE)   // 53760

// ---- popc engine (threads 256-511): 112M x 128N, full K resident
#define PX_WD_BYTES (A_POPC * 8)            // 896 per word
#define SM_PX_OFF  SM_MMA_BYTES             // 32 wd x 896 = 28672
#define SM_PW_OFF  (SM_PX_OFF + 28672)      // 32 wd x 128 x 8 = 32768

// ---- dp4a engine (threads 512-639): 48M x 128N, 2-stage, pitch 72
#define DP_PITCH  72
#define DP_A_BYTES (A_DP * DP_PITCH)        // 3456
#define DP_B_BYTES (128 * DP_PITCH)         // 9216
#define DP_STAGE  (DP_A_BYTES + DP_B_BYTES) // 12672
#define SM_DP_OFF  (SM_PW_OFF + 32768)      // 115200
#define SMEM_TOTAL (SM_DP_OFF + 2 * DP_STAGE) // 140544

#define N_TILES   8
#define TOTAL_CTAS (MT * N_TILES)           // 1024
#define THREADS   640

// ============================================================================
// Scratch (device globals — no runtime allocation)
// ============================================================================
__device__ int8_t g_xq[(size_t)M_TOTAL * K_TOTAL];    // 32 MiB (mma+dp ranges used)
__device__ int8_t g_wq[(size_t)N_TOTAL * K_TOTAL];    // 1 MiB
__device__ uint2  g_xpk[(size_t)NWORDS * M_POPC_TOT]; // 3.5 MiB [wd][r]
__device__ uint2  g_wpk[(size_t)NWORDS * N_TOTAL];    // 256 KiB [wd][c]

// ============================================================================
// Helpers
// ============================================================================
__device__ __forceinline__ uint32_t smem_u32(const void* p) {
    uint32_t a;
    asm("{ .reg .u64 t; cvta.to.shared.u64 t, %1; cvt.u32.u64 %0, t; }"
        : "=r"(a) : "l"(p));
    return a;
}

#define CP_ASYNC16(dst_u32, gsrc) \
    asm volatile("cp.async.cg.shared.global [%0], [%1], 16;" \
                 :: "r"(dst_u32), "l"(gsrc) : "memory")
#define CP_ASYNC8(dst_u32, gsrc) \
    asm volatile("cp.async.ca.shared.global [%0], [%1], 8;" \
                 :: "r"(dst_u32), "l"(gsrc) : "memory")
#define CP_ASYNC_COMMIT() asm volatile("cp.async.commit_group;" ::: "memory")
#define CP_ASYNC_WAIT(n)  asm volatile("cp.async.wait_group %0;" :: "n"(n) : "memory")
#define BAR(id, cnt) asm volatile("bar.sync %0, %1;" :: "n"(id), "n"(cnt) : "memory")

__device__ __forceinline__ void mma_s8(int* c, const uint32_t* a, const uint32_t* b) {
    asm volatile(
        "mma.sync.aligned.m16n8k32.row.col.s32.s8.s8.s32 "
        "{%0,%1,%2,%3}, {%4,%5,%6,%7}, {%8,%9}, {%0,%1,%2,%3};"
        : "+r"(c[0]), "+r"(c[1]), "+r"(c[2]), "+r"(c[3])
        : "r"(a[0]), "r"(a[1]), "r"(a[2]), "r"(a[3]), "r"(b[0]), "r"(b[1]));
}

__device__ __forceinline__ void ldsm_x4(uint32_t* r, uint32_t addr) {
    asm volatile("ldmatrix.sync.aligned.m8n8.x4.shared.b16 {%0,%1,%2,%3}, [%4];"
        : "=r"(r[0]), "=r"(r[1]), "=r"(r[2]), "=r"(r[3]) : "r"(addr));
}

__device__ __forceinline__ int8_t tq(float v) {
    return (fabsf(v) < THRESH) ? (int8_t)0 : (v > 0.f ? (int8_t)1 : (int8_t)-1);
}

// ============================================================================
// Prep (ONE kernel, each x row touched exactly once):
//   int8 quantize: x rows [0,12288) + [26624,32768) + all w
//   bit-pack:      x rows [12288,26624) + all w
// ============================================================================
#define N16_A (M_MMA_TOT * (K_TOTAL / 16))   // 786432
#define N16_D (M_DP_TOT * (K_TOTAL / 16))    // 393216
#define N16_W ((N_TOTAL * K_TOTAL) / 16)     // 65536
#define PK_X  (M_POPC_TOT * NWORDS)          // 458752
#define PK_W  (N_TOTAL * NWORDS)             // 32768
#define PREP_TOTAL (N16_A + N16_D + N16_W + PK_X + PK_W)

__global__ __launch_bounds__(256) void prep_kernel(
    const float* __restrict__ x, const float* __restrict__ w)
{
    int i = blockIdx.x * blockDim.x + threadIdx.x;
    if (i >= PREP_TOTAL) return;

    if (i < N16_A + N16_D + N16_W) {
        // ---- int8 quantize, 16 elems/thread
        const float4* src;
        int4* dst;
        if (i < N16_A) {
            src = (const float4*)x + i * 4;
            dst = (int4*)g_xq + i;
        } else if (i < N16_A + N16_D) {
            size_t idx16 = (size_t)R_DP0 * (K_TOTAL / 16) + (i - N16_A);
            src = (const float4*)x + idx16 * 4;
            dst = (int4*)g_xq + idx16;
        } else {
            int j = i - N16_A - N16_D;
            src = (const float4*)w + (size_t)j * 4;
            dst = (int4*)g_wq + j;
        }
        int8_t r[16];
        #pragma unroll
        for (int j = 0; j < 4; j++) {
            float4 v = src[j];
            r[j * 4 + 0] = tq(v.x); r[j * 4 + 1] = tq(v.y);
            r[j * 4 + 2] = tq(v.z); r[j * 4 + 3] = tq(v.w);
        }
        *dst = *reinterpret_cast<int4*>(r);
    } else {
        // ---- bit-pack 32 floats -> (e,n) masks
        int t = i - (N16_A + N16_D + N16_W);
        const float4* p;
        uint2* dst;
        if (t < PK_X) {
            int r = t % M_POPC_TOT, wd = t / M_POPC_TOT;
            p = (const float4*)(x + (size_t)(R_POPC0 + r) * K_TOTAL + wd * 32);
            dst = g_xpk + (size_t)wd * M_POPC_TOT + r;
        } else {
            int j = t - PK_X;
            int c = j & (N_TOTAL - 1), wd = j >> 10;
            p = (const float4*)(w + (size_t)c * K_TOTAL + wd * 32);
            dst = g_wpk + (size_t)wd * N_TOTAL + c;
        }
        uint32_t e = 0, n = 0;
        #pragma unroll
        for (int j = 0; j < 8; j++) {
            float4 v = p[j];
            float f[4] = {v.x, v.y, v.z, v.w};
            #pragma unroll
            for (int q = 0; q < 4; q++) {
                uint32_t nz = (fabsf(f[q]) >= THRESH) ? 1u : 0u;
                uint32_t ng = (nz && f[q] < 0.f) ? 1u : 0u;
                e |= nz << (j * 4 + q);
                n |= ng << (j * 4 + q);
            }
        }
        *dst = make_uint2(e, n);
    }
}

// ============================================================================
// Fused GEMM: 640 threads. Per SMSP: 2 mma + 2 popc + 1 dp4a warps.
//   tid 0-255  : mma.sync (tensor pipe)  rows [0, 12288)
//   tid 256-511: popcount (popc pipe)    rows [12288, 26624)
//   tid 512-639: dp4a     (fma pipe)     rows [26624, 32768)
// Engines fully decoupled (separate named barriers, separate SMEM).
// ============================================================================
__global__ __launch_bounds__(THREADS, 1) void ternary_gemm_kernel(float* __restrict__ out)
{
    extern __shared__ char smem[];
    const int tid = threadIdx.x;
    const int c = (int)blockIdx.x;
    const int n0 = (c & 7) * 128;
    const int mt = c >> 3;                 // 0..127
    const uint32_t sbase = smem_u32(smem);

    if (tid < 256) {
        // ===================== MMA ENGINE (96x128) — R14 proven ===========
        const int lane = tid & 31;
        const int wid  = tid >> 5;
        const int wn   = wid & 3;          // 4 n-cols of 32
        const int wm   = wid >> 2;         // 2 m-rows of 48
        const int m0   = mt * A_MMA;

        const uint64_t xg = __cvta_generic_to_global(g_xq);
        const uint64_t wg = __cvta_generic_to_global(g_wq);

        const int g8 = lane >> 3, t8 = lane & 7;
        const uint32_t a_lane = (uint32_t)((t8 + ((g8 & 1) << 3)) * PITCH + ((g8 >> 1) << 4));
        const uint32_t b_lane = (uint32_t)((t8 + ((g8 >> 1) << 3)) * PITCH + ((g8 & 1) << 4));

        auto load_stage = [&](int kc, int s) {
            uint32_t sb = sbase + s * MMA_STAGE;
            #pragma unroll
            for (int t = 0; t < 4; t++) {          // 896 chunks of 16B
                int i = tid + t * 256;
                if (i < 384) {                     // A: 96 rows x 4 seg
                    int row = i >> 2, seg = i & 3;
                    uint64_t src = xg + (uint64_t)(m0 + row) * K_TOTAL + kc * TILE_K + seg * 16;
                    CP_ASYNC16(sb + row * PITCH + seg * 16, src);
                } else if (i < 896) {              // B: 128 rows x 4 seg
                    int j = i - 384;
                    int row = j >> 2, seg = j & 3;
                    uint64_t src = wg + (uint64_t)(n0 + row) * K_TOTAL + kc * TILE_K + seg * 16;
                    CP_ASYNC16(sb + (A_MMA + row) * PITCH + seg * 16, src);
                }
            }
            CP_ASYNC_COMMIT();
        };

        int acc[3][4][4];
        #pragma unroll
        for (int mi = 0; mi < 3; mi++)
            #pragma unroll
            for (int ni = 0; ni < 4; ni++)
                #pragma unroll
                for (int q = 0; q < 4; q++) acc[mi][ni][q] = 0;

        load_stage(0, 0);
        load_stage(1, 1);

        for (int kc = 0; kc < NUM_KC; kc++) {
            if (kc + STAGES - 1 < NUM_KC) CP_ASYNC_WAIT(STAGES - 2);
            else                          CP_ASYNC_WAIT(0);
            BAR(1, 256);

            const uint32_t stage = sbase + (kc % STAGES) * MMA_STAGE;
            const uint32_t sa  = stage + (uint32_t)(wm * 48) * PITCH + a_lane;
            const uint32_t sbB = stage + (uint32_t)(A_MMA + wn * 32) * PITCH + b_lane;

            #pragma unroll
            for (int kk = 0; kk < 2; kk++) {
                const uint32_t ko = (uint32_t)(kk * 32);
                uint32_t a[3][4];
                #pragma unroll
                for (int mi = 0; mi < 3; mi++)
                    ldsm_x4(a[mi], sa + (uint32_t)(mi * 16) * PITCH + ko);
                uint32_t b[2][4];
                #pragma unroll
                for (int p = 0; p < 2; p++)
                    ldsm_x4(b[p], sbB + (uint32_t)(p * 16) * PITCH + ko);
                #pragma unroll
                for (int mi = 0; mi < 3; mi++)
                    #pragma unroll
                    for (int ni = 0; ni < 4; ni++)
                        mma_s8(acc[mi][ni], a[mi], &b[ni >> 1][(ni & 1) * 2]);
            }
            BAR(1, 256);

            if (kc + STAGES - 1 < NUM_KC)
                load_stage(kc + STAGES - 1, (kc + STAGES - 1) % STAGES);
        }

        #pragma unroll
        for (int mi = 0; mi < 3; mi++) {
            const int r = m0 + wm * 48 + mi * 16 + (lane >> 2);
            #pragma unroll
            for (int ni = 0; ni < 4; ni++) {
                const int cc = n0 + wn * 32 + ni * 8 + (lane & 3) * 2;
                float2 v0 = make_float2((float)acc[mi][ni][0], (float)acc[mi][ni][1]);
                float2 v1 = make_float2((float)acc[mi][ni][2], (float)acc[mi][ni][3]);
                *(float2*)(out + (size_t)r * N_TOTAL + cc)       = v0;
                *(float2*)(out + (size_t)(r + 8) * N_TOTAL + cc) = v1;
            }
        }
    } else if (tid < 512) {
        // ===================== POPC ENGINE (112x128) ======================
        const int ptid = tid - 256;        // 0..255
        const int tx = ptid & 15;          // col = tx + 16j
        const int ty = ptid >> 4;          // 0..15, rows ty*7..+6
        const int r0 = mt * A_POPC;

        const uint64_t xg = __cvta_generic_to_global(g_xpk);
        const uint64_t wg = __cvta_generic_to_global(g_wpk);
        const uint32_t px = sbase + SM_PX_OFF;   // [wd][112 rows] uint2
        const uint32_t pw = sbase + SM_PW_OFF;   // [wd][128 cols] uint2

        #pragma unroll
        for (int t = 0; t < 7; t++) {            // x: 1792 x 16B (2 rows/chunk)
            int i = ptid + t * 256;
            int wd = i / 56, off = i % 56;
            uint64_t src = xg + ((uint64_t)wd * M_POPC_TOT + r0 + off * 2) * 8;
            CP_ASYNC16(px + wd * PX_WD_BYTES + off * 16, src);
        }
        #pragma unroll
        for (int t = 0; t < 8; t++) {            // w: 2048 x 16B
            int i = ptid + t * 256;
            int wd = i >> 6, off = i & 63;
            uint64_t src = wg + ((uint64_t)wd * N_TOTAL + n0 + off * 2) * 8;
            CP_ASYNC16(pw + wd * 1024 + off * 16, src);
        }
        CP_ASYNC_COMMIT();
        CP_ASYNC_WAIT(0);
        BAR(2, 256);

        int acc[7][8];
        #pragma unroll
        for (int i = 0; i < 7; i++)
            #pragma unroll
            for (int j = 0; j < 8; j++) acc[i][j] = 0;

        const char* xb = smem + SM_PX_OFF + ty * 56;   // 7 rows x 8B
        const char* wb = smem + SM_PW_OFF + tx * 8;    // cols tx + 16j

        #pragma unroll 2
        for (int wd = 0; wd < NWORDS; wd++) {
            uint2 xr[7];
            #pragma unroll
            for (int q = 0; q < 7; q++)
                xr[q] = *(const uint2*)(xb + wd * PX_WD_BYTES + q * 8);
            #pragma unroll
            for (int j = 0; j < 8; j++) {
                uint2 wcv = *(const uint2*)(wb + wd * 1024 + j * 128);
                #pragma unroll
                for (int i = 0; i < 7; i++) {
                    uint32_t t = xr[i].x & wcv.x;
                    uint32_t d = t & (xr[i].y ^ wcv.y);
                    acc[i][j] += __popc(t) - 2 * __popc(d);
                }
            }
        }

        #pragma unroll
        for (int i = 0; i < 7; i++) {
            const int r = R_POPC0 + r0 + ty * 7 + i;
            float* prow = out + (size_t)r * N_TOTAL + n0 + tx;
            #pragma unroll
            for (int j = 0; j < 8; j++)
                prow[j * 16] = (float)acc[i][j];
        }
    } else {
        // ===================== DP4A ENGINE (48x128) =======================
        const int dtid = tid - 512;        // 0..127
        const int tx = dtid & 15;          // col = tx + 16j
        const int ty = dtid >> 4;          // 0..7, rows ty*6..+5
        const int m0 = R_DP0 + mt * A_DP;

        const uint64_t xg = __cvta_generic_to_global(g_xq);
        const uint64_t wg = __cvta_generic_to_global(g_wq);
        const uint32_t dbase = sbase + SM_DP_OFF;

        auto load_dp = [&](int kc, int s) {
            uint32_t sa = dbase + s * DP_STAGE;
            uint32_t sb = sa + DP_A_BYTES;
            #pragma unroll
            for (int t = 0; t < 11; t++) {         // 1408 chunks of 8B
                int i = dtid + t * 128;
                if (i < 384) {                     // A: 48 rows x 8 seg
                    int row = i >> 3, seg = i & 7;
                    uint64_t src = xg + (uint64_t)(m0 + row) * K_TOTAL + kc * 64 + seg * 8;
                    CP_ASYNC8(sa + row * DP_PITCH + seg * 8, src);
                } else {                           // B: 128 cols x 8 seg
                    int j = i - 384;
                    int col = j >> 3, seg = j & 7;
                    uint64_t src = wg + (uint64_t)(n0 + col) * K_TOTAL + kc * 64 + seg * 8;
                    CP_ASYNC8(sb + col * DP_PITCH + seg * 8, src);
                }
            }
            CP_ASYNC_COMMIT();
        };

        int acc[6][8];
        #pragma unroll
        for (int i = 0; i < 6; i++)
            #pragma unroll
            for (int j = 0; j < 8; j++) acc[i][j] = 0;

        load_dp(0, 0);

        #pragma unroll 1
        for (int kc = 0; kc < NUM_KC; kc++) {
            const int s = kc & 1;
            if (kc + 1 < NUM_KC) { load_dp(kc + 1, s ^ 1); CP_ASYNC_WAIT(1); }
            else                 { CP_ASYNC_WAIT(0); }
            BAR(3, 128);

            const char* aS = smem + SM_DP_OFF + s * DP_STAGE + (ty * 6) * DP_PITCH;
            const char* bS = smem + SM_DP_OFF + s * DP_STAGE + DP_A_BYTES + tx * DP_PITCH;

            #pragma unroll 2
            for (int g = 0; g < 8; g++) {          // 8B K-groups
                int2 aa[6];
                #pragma unroll
                for (int i = 0; i < 6; i++)
                    aa[i] = *(const int2*)(aS + i * DP_PITCH + g * 8);
                #pragma unroll
                for (int j = 0; j < 8; j++) {
                    int2 bb = *(const int2*)(bS + j * (16 * DP_PITCH) + g * 8);
                    #pragma unroll
                    for (int i = 0; i < 6; i++) {
                        int sum = acc[i][j];
                        sum = __dp4a(aa[i].x, bb.x, sum);
                        sum = __dp4a(aa[i].y, bb.y, sum);
                        acc[i][j] = sum;
                    }
                }
            }
            BAR(3, 128);
        }

        #pragma unroll
        for (int i = 0; i < 6; i++) {
            const int r = m0 + ty * 6 + i;
            float* prow = out + (size_t)r * N_TOTAL + n0 + tx;
            #pragma unroll
            for (int j = 0; j < 8; j++)
                prow[j * 16] = (float)acc[i][j];
        }
    }
}

// ============================================================================
// Launch (2 launches per call -> GEMM lands in the ncu profile slot)
// ============================================================================
extern "C" void kernel_launch(void* const* d_in, const int* in_sizes, int n_in,
                              void* d_out, int out_size)
{
    const float* x = (const float*)d_in[0];
    const float* w = (const float*)d_in[1];
    float* out = (float*)d_out;

    prep_kernel<<<(PREP_TOTAL + 255) / 256, 256>>>(x, w);

    static bool attr_set = false;
    if (!attr_set) {
        cudaFuncSetAttribute(ternary_gemm_kernel,
                             cudaFuncAttributeMaxDynamicSharedMemorySize, SMEM_TOTAL);
        attr_set = true;
    }
    ternary_gemm_kernel<<<TOTAL_CTAS, THREADS, SMEM_TOTAL>>>(out);
}

// round 17
// speedup vs baseline: 1.1738x; 1.0583x over previous
#include <cuda_runtime.h>
#include <cstdint>

// ============================================================================
// Problem constants
// ============================================================================
#define M_TOTAL   32768
#define N_TOTAL   1024
#define K_TOTAL   1024
#define THRESH    0.05f

// ---- per-CTA row split: mma 96, popc 128, dp4a 32  (x 128 m-tiles) [R14 best]
#define MT        128
#define A_MMA     96
#define A_POPC    128
#define A_DP      32
#define M_MMA_TOT   (MT * A_MMA)            // 12288
#define M_POPC_TOT  (MT * A_POPC)           // 16384
#define M_DP_TOT    (MT * A_DP)             // 4096
#define R_POPC0   M_MMA_TOT                 // 12288
#define R_DP0     (M_MMA_TOT + M_POPC_TOT)  // 28672

#define NWORDS    32

// ---- mma engine (threads 0-255): 96M x 128N, 3-stage cp.async
#define TILE_K    64
#define NUM_KC    (K_TOTAL / TILE_K)        // 16
#define STAGES    3
#define PITCH     80
#define MMA_STAGE ((A_MMA + 128) * PITCH)   // 17920
#define SM_MMA_BYTES (STAGES * MMA_STAGE)   // 53760

// ---- popc engine (threads 256-511): 128M x 128N, full K resident
#define SM_PX_OFF  SM_MMA_BYTES             // x: 32 wd x 128 rows x 8B = 32768
#define SM_PW_OFF  (SM_PX_OFF + 32768)      // w: 32 wd x 128 cols x 8B = 32768

// ---- dp4a engine (threads 512-639): 32M x 128N, 2-stage, pitch 72
#define DP_PITCH  72
#define DP_A_BYTES (A_DP * DP_PITCH)        // 2304
#define DP_B_BYTES (128 * DP_PITCH)         // 9216
#define DP_STAGE  (DP_A_BYTES + DP_B_BYTES) // 11520
#define SM_DP_OFF  (SM_PW_OFF + 32768)      // 119296
#define SMEM_TOTAL (SM_DP_OFF + 2 * DP_STAGE) // 142336

#define N_TILES   8
#define TOTAL_CTAS (MT * N_TILES)           // 1024
#define THREADS   640

// ============================================================================
// Scratch (device globals — no runtime allocation)
// ============================================================================
__device__ int8_t g_xq[(size_t)M_TOTAL * K_TOTAL];    // 32 MiB (mma+dp ranges used)
__device__ int8_t g_wq[(size_t)N_TOTAL * K_TOTAL];    // 1 MiB
__device__ uint2  g_xpk[(size_t)NWORDS * M_POPC_TOT]; // 4 MiB [wd][r]
__device__ uint2  g_wpk[(size_t)NWORDS * N_TOTAL];    // 256 KiB [wd][c]

// ============================================================================
// Helpers
// ============================================================================
__device__ __forceinline__ uint32_t smem_u32(const void* p) {
    uint32_t a;
    asm("{ .reg .u64 t; cvta.to.shared.u64 t, %1; cvt.u32.u64 %0, t; }"
        : "=r"(a) : "l"(p));
    return a;
}

#define CP_ASYNC16(dst_u32, gsrc) \
    asm volatile("cp.async.cg.shared.global [%0], [%1], 16;" \
                 :: "r"(dst_u32), "l"(gsrc) : "memory")
#define CP_ASYNC8(dst_u32, gsrc) \
    asm volatile("cp.async.ca.shared.global [%0], [%1], 8;" \
                 :: "r"(dst_u32), "l"(gsrc) : "memory")
#define CP_ASYNC_COMMIT() asm volatile("cp.async.commit_group;" ::: "memory")
#define CP_ASYNC_WAIT(n)  asm volatile("cp.async.wait_group %0;" :: "n"(n) : "memory")
#define BAR(id, cnt) asm volatile("bar.sync %0, %1;" :: "n"(id), "n"(cnt) : "memory")

__device__ __forceinline__ void mma_s8(int* c, const uint32_t* a, const uint32_t* b) {
    asm volatile(
        "mma.sync.aligned.m16n8k32.row.col.s32.s8.s8.s32 "
        "{%0,%1,%2,%3}, {%4,%5,%6,%7}, {%8,%9}, {%0,%1,%2,%3};"
        : "+r"(c[0]), "+r"(c[1]), "+r"(c[2]), "+r"(c[3])
        : "r"(a[0]), "r"(a[1]), "r"(a[2]), "r"(a[3]), "r"(b[0]), "r"(b[1]));
}

__device__ __forceinline__ void ldsm_x4(uint32_t* r, uint32_t addr) {
    asm volatile("ldmatrix.sync.aligned.m8n8.x4.shared.b16 {%0,%1,%2,%3}, [%4];"
        : "=r"(r[0]), "=r"(r[1]), "=r"(r[2]), "=r"(r[3]) : "r"(addr));
}

__device__ __forceinline__ int8_t tq(float v) {
    return (fabsf(v) < THRESH) ? (int8_t)0 : (v > 0.f ? (int8_t)1 : (int8_t)-1);
}

// ============================================================================
// Prep 1: int8 quantize — x rows [0,12288) + [28672,32768) + all w (single touch)
// ============================================================================
#define N16_A (M_MMA_TOT * (K_TOTAL / 16))   // 786432
#define N16_D (M_DP_TOT * (K_TOTAL / 16))    // 262144
#define N16_W ((N_TOTAL * K_TOTAL) / 16)     // 65536
#define N16_TOTAL (N16_A + N16_D + N16_W)

__global__ __launch_bounds__(256) void prep_q_kernel(
    const float* __restrict__ x, const float* __restrict__ w)
{
    int i = blockIdx.x * blockDim.x + threadIdx.x;
    if (i >= N16_TOTAL) return;
    const float4* src;
    int4* dst;
    if (i < N16_A) {
        src = (const float4*)x + i * 4;
        dst = (int4*)g_xq + i;
    } else if (i < N16_A + N16_D) {
        size_t idx16 = (size_t)R_DP0 * (K_TOTAL / 16) + (i - N16_A);
        src = (const float4*)x + idx16 * 4;
        dst = (int4*)g_xq + idx16;
    } else {
        int j = i - N16_A - N16_D;
        src = (const float4*)w + (size_t)j * 4;
        dst = (int4*)g_wq + j;
    }
    int8_t r[16];
    #pragma unroll
    for (int j = 0; j < 4; j++) {
        float4 v = src[j];
        r[j * 4 + 0] = tq(v.x); r[j * 4 + 1] = tq(v.y);
        r[j * 4 + 2] = tq(v.z); r[j * 4 + 3] = tq(v.w);
    }
    *dst = *reinterpret_cast<int4*>(r);
}

// ============================================================================
// Prep 2: bit-pack — x rows [12288, 28672) -> g_xpk, all w -> g_wpk
// ============================================================================
#define PK_X (M_POPC_TOT * NWORDS)   // 524288
#define PK_W (N_TOTAL * NWORDS)      // 32768
#define PK_TOTAL (PK_X + PK_W)

__global__ __launch_bounds__(256) void prep_pk_kernel(
    const float* __restrict__ x, const float* __restrict__ w)
{
    int t = blockIdx.x * blockDim.x + threadIdx.x;
    if (t >= PK_TOTAL) return;
    const float4* p;
    uint2* dst;
    if (t < PK_X) {
        int r = t & (M_POPC_TOT - 1), wd = t >> 14;
        p = (const float4*)(x + (size_t)(R_POPC0 + r) * K_TOTAL + wd * 32);
        dst = g_xpk + (size_t)wd * M_POPC_TOT + r;
    } else {
        int j = t - PK_X;
        int c = j & (N_TOTAL - 1), wd = j >> 10;
        p = (const float4*)(w + (size_t)c * K_TOTAL + wd * 32);
        dst = g_wpk + (size_t)wd * N_TOTAL + c;
    }
    uint32_t e = 0, n = 0;
    #pragma unroll
    for (int j = 0; j < 8; j++) {
        float4 v = p[j];
        float f[4] = {v.x, v.y, v.z, v.w};
        #pragma unroll
        for (int q = 0; q < 4; q++) {
            uint32_t nz = (fabsf(f[q]) >= THRESH) ? 1u : 0u;
            uint32_t ng = (nz && f[q] < 0.f) ? 1u : 0u;
            e |= nz << (j * 4 + q);
            n |= ng << (j * 4 + q);
        }
    }
    *dst = make_uint2(e, n);
}

// ============================================================================
// Fused GEMM (R14 config): 640 threads. Per SMSP: 2 mma + 2 popc + 1 dp4a.
//   tid 0-255  : mma.sync (tensor pipe)  rows [0, 12288)
//   tid 256-511: popcount (popc pipe)    rows [12288, 28672)
//   tid 512-639: dp4a     (fma pipe)     rows [28672, 32768)
// mma loop: TOP barrier only (3-stage: refilled stage's readers all finished
// before this iteration's top barrier — bottom barrier is redundant).
// ============================================================================
__global__ __launch_bounds__(THREADS, 1) void ternary_gemm_kernel(float* __restrict__ out)
{
    extern __shared__ char smem[];
    const int tid = threadIdx.x;
    const int c = (int)blockIdx.x;
    const int n0 = (c & 7) * 128;
    const int mt = c >> 3;                 // 0..127
    const uint32_t sbase = smem_u32(smem);

    if (tid < 256) {
        // ===================== MMA ENGINE (96x128) =====================
        const int lane = tid & 31;
        const int wid  = tid >> 5;
        const int wn   = wid & 3;          // 4 n-cols of 32
        const int wm   = wid >> 2;         // 2 m-rows of 48
        const int m0   = mt * A_MMA;

        const uint64_t xg = __cvta_generic_to_global(g_xq);
        const uint64_t wg = __cvta_generic_to_global(g_wq);

        const int g8 = lane >> 3, t8 = lane & 7;
        const uint32_t a_lane = (uint32_t)((t8 + ((g8 & 1) << 3)) * PITCH + ((g8 >> 1) << 4));
        const uint32_t b_lane = (uint32_t)((t8 + ((g8 >> 1) << 3)) * PITCH + ((g8 & 1) << 4));

        auto load_stage = [&](int kc, int s) {
            uint32_t sb = sbase + s * MMA_STAGE;
            #pragma unroll
            for (int t = 0; t < 4; t++) {          // 896 chunks of 16B
                int i = tid + t * 256;
                if (i < 384) {                     // A: 96 rows x 4 seg
                    int row = i >> 2, seg = i & 3;
                    uint64_t src = xg + (uint64_t)(m0 + row) * K_TOTAL + kc * TILE_K + seg * 16;
                    CP_ASYNC16(sb + row * PITCH + seg * 16, src);
                } else if (i < 896) {              // B: 128 rows x 4 seg
                    int j = i - 384;
                    int row = j >> 2, seg = j & 3;
                    uint64_t src = wg + (uint64_t)(n0 + row) * K_TOTAL + kc * TILE_K + seg * 16;
                    CP_ASYNC16(sb + (A_MMA + row) * PITCH + seg * 16, src);
                }
            }
            CP_ASYNC_COMMIT();
        };

        int acc[3][4][4];
        #pragma unroll
        for (int mi = 0; mi < 3; mi++)
            #pragma unroll
            for (int ni = 0; ni < 4; ni++)
                #pragma unroll
                for (int q = 0; q < 4; q++) acc[mi][ni][q] = 0;

        load_stage(0, 0);
        load_stage(1, 1);

        for (int kc = 0; kc < NUM_KC; kc++) {
            if (kc + STAGES - 1 < NUM_KC) CP_ASYNC_WAIT(STAGES - 2);
            else                          CP_ASYNC_WAIT(0);
            BAR(1, 256);   // data ready AND prior iteration's reads complete

            const uint32_t stage = sbase + (kc % STAGES) * MMA_STAGE;
            const uint32_t sa  = stage + (uint32_t)(wm * 48) * PITCH + a_lane;
            const uint32_t sbB = stage + (uint32_t)(A_MMA + wn * 32) * PITCH + b_lane;

            #pragma unroll
            for (int kk = 0; kk < 2; kk++) {
                const uint32_t ko = (uint32_t)(kk * 32);
                uint32_t a[3][4];
                #pragma unroll
                for (int mi = 0; mi < 3; mi++)
                    ldsm_x4(a[mi], sa + (uint32_t)(mi * 16) * PITCH + ko);
                uint32_t b[2][4];
                #pragma unroll
                for (int p = 0; p < 2; p++)
                    ldsm_x4(b[p], sbB + (uint32_t)(p * 16) * PITCH + ko);
                #pragma unroll
                for (int mi = 0; mi < 3; mi++)
                    #pragma unroll
                    for (int ni = 0; ni < 4; ni++)
                        mma_s8(acc[mi][ni], a[mi], &b[ni >> 1][(ni & 1) * 2]);
            }

            // no bottom barrier: stage (kc+2)%3 == stage read at iter kc-1,
            // whose reads completed before this iteration's TOP barrier.
            if (kc + STAGES - 1 < NUM_KC)
                load_stage(kc + STAGES - 1, (kc + STAGES - 1) % STAGES);
        }

        #pragma unroll
        for (int mi = 0; mi < 3; mi++) {
            const int r = m0 + wm * 48 + mi * 16 + (lane >> 2);
            #pragma unroll
            for (int ni = 0; ni < 4; ni++) {
                const int cc = n0 + wn * 32 + ni * 8 + (lane & 3) * 2;
                float2 v0 = make_float2((float)acc[mi][ni][0], (float)acc[mi][ni][1]);
                float2 v1 = make_float2((float)acc[mi][ni][2], (float)acc[mi][ni][3]);
                *(float2*)(out + (size_t)r * N_TOTAL + cc)       = v0;
                *(float2*)(out + (size_t)(r + 8) * N_TOTAL + cc) = v1;
            }
        }
    } else if (tid < 512) {
        // ===================== POPC ENGINE (128x128) — R8/R14 proven ======
        const int ptid = tid - 256;        // 0..255
        const int tx = ptid & 15;          // col = tx + 16j
        const int ty = ptid >> 4;          // rows ty*8..+7
        const int r0 = mt * A_POPC;

        const uint64_t xg = __cvta_generic_to_global(g_xpk);
        const uint64_t wg = __cvta_generic_to_global(g_wpk);
        const uint32_t px = sbase + SM_PX_OFF;   // [wd][128 rows] uint2
        const uint32_t pw = sbase + SM_PW_OFF;   // [wd][128 cols] uint2

        #pragma unroll
        for (int t = 0; t < 8; t++) {            // x: 2048 x 16B
            int i = ptid + t * 256;
            int wd = i >> 6, off = i & 63;
            uint64_t src = xg + ((uint64_t)wd * M_POPC_TOT + r0 + off * 2) * 8;
            CP_ASYNC16(px + wd * 1024 + off * 16, src);
        }
        #pragma unroll
        for (int t = 0; t < 8; t++) {            // w: 2048 x 16B
            int i = ptid + t * 256;
            int wd = i >> 6, off = i & 63;
            uint64_t src = wg + ((uint64_t)wd * N_TOTAL + n0 + off * 2) * 8;
            CP_ASYNC16(pw + wd * 1024 + off * 16, src);
        }
        CP_ASYNC_COMMIT();
        CP_ASYNC_WAIT(0);
        BAR(2, 256);

        int acc[8][8];
        #pragma unroll
        for (int i = 0; i < 8; i++)
            #pragma unroll
            for (int j = 0; j < 8; j++) acc[i][j] = 0;

        const char* xb = smem + SM_PX_OFF + ty * 64;     // 8 rows x 8B
        const char* wb = smem + SM_PW_OFF + tx * 8;      // cols tx + 16j

        #pragma unroll 1
        for (int wd = 0; wd < NWORDS; wd++) {
            int4 xr[4];
            #pragma unroll
            for (int q = 0; q < 4; q++)
                xr[q] = *(const int4*)(xb + wd * 1024 + q * 16);
            uint2 wc[8];
            #pragma unroll
            for (int j = 0; j < 8; j++)
                wc[j] = *(const uint2*)(wb + wd * 1024 + j * 128);

            #pragma unroll
            for (int i = 0; i < 8; i++) {
                const uint32_t xe = (i & 1) ? (uint32_t)xr[i >> 1].z : (uint32_t)xr[i >> 1].x;
                const uint32_t xn = (i & 1) ? (uint32_t)xr[i >> 1].w : (uint32_t)xr[i >> 1].y;
                #pragma unroll
                for (int j = 0; j < 8; j++) {
                    uint32_t t = xe & wc[j].x;
                    uint32_t d = t & (xn ^ wc[j].y);
                    acc[i][j] += __popc(t) - 2 * __popc(d);
                }
            }
        }

        #pragma unroll
        for (int i = 0; i < 8; i++) {
            const int r = R_POPC0 + r0 + ty * 8 + i;
            float* prow = out + (size_t)r * N_TOTAL + n0 + tx;
            #pragma unroll
            for (int j = 0; j < 8; j++)
                prow[j * 16] = (float)acc[i][j];
        }
    } else {
        // ===================== DP4A SIDE-CAR (32x128) — R14 proven ========
        const int dtid = tid - 512;        // 0..127
        const int tx = dtid & 15;          // col = tx + 16j
        const int ty = dtid >> 4;          // 0..7, rows ty*4..+3
        const int m0 = R_DP0 + mt * A_DP;

        const uint64_t xg = __cvta_generic_to_global(g_xq);
        const uint64_t wg = __cvta_generic_to_global(g_wq);
        const uint32_t dbase = sbase + SM_DP_OFF;

        auto load_dp = [&](int kc, int s) {
            uint32_t sa = dbase + s * DP_STAGE;
            uint32_t sb = sa + DP_A_BYTES;
            #pragma unroll
            for (int t = 0; t < 10; t++) {         // 1280 chunks of 8B
                int i = dtid + t * 128;
                if (i < 256) {                     // A: 32 rows x 8 seg
                    int row = i >> 3, seg = i & 7;
                    uint64_t src = xg + (uint64_t)(m0 + row) * K_TOTAL + kc * 64 + seg * 8;
                    CP_ASYNC8(sa + row * DP_PITCH + seg * 8, src);
                } else {                           // B: 128 cols x 8 seg
                    int j = i - 256;
                    int col = j >> 3, seg = j & 7;
                    uint64_t src = wg + (uint64_t)(n0 + col) * K_TOTAL + kc * 64 + seg * 8;
                    CP_ASYNC8(sb + col * DP_PITCH + seg * 8, src);
                }
            }
            CP_ASYNC_COMMIT();
        };

        int acc[4][8];
        #pragma unroll
        for (int i = 0; i < 4; i++)
            #pragma unroll
            for (int j = 0; j < 8; j++) acc[i][j] = 0;

        load_dp(0, 0);

        #pragma unroll 1
        for (int kc = 0; kc < NUM_KC; kc++) {
            const int s = kc & 1;
            if (kc + 1 < NUM_KC) { load_dp(kc + 1, s ^ 1); CP_ASYNC_WAIT(1); }
            else                 { CP_ASYNC_WAIT(0); }
            BAR(3, 128);

            const char* aS = smem + SM_DP_OFF + s * DP_STAGE + (ty * 4) * DP_PITCH;
            const char* bS = smem + SM_DP_OFF + s * DP_STAGE + DP_A_BYTES + tx * DP_PITCH;

            #pragma unroll 2
            for (int g = 0; g < 8; g++) {          // 8B K-groups
                int2 bb[8];
                #pragma unroll
                for (int j = 0; j < 8; j++)
                    bb[j] = *(const int2*)(bS + j * (16 * DP_PITCH) + g * 8);
                #pragma unroll
                for (int i = 0; i < 4; i++) {
                    int2 aa = *(const int2*)(aS + i * DP_PITCH + g * 8);
                    #pragma unroll
                    for (int j = 0; j < 8; j++) {
                        int sum = acc[i][j];
                        sum = __dp4a(aa.x, bb[j].x, sum);
                        sum = __dp4a(aa.y, bb[j].y, sum);
                        acc[i][j] = sum;
                    }
                }
            }
            BAR(3, 128);   // 2-stage: required before next iteration's load
        }

        #pragma unroll
        for (int i = 0; i < 4; i++) {
            const int r = m0 + ty * 4 + i;
            float* prow = out + (size_t)r * N_TOTAL + n0 + tx;
            #pragma unroll
            for (int j = 0; j < 8; j++)
                prow[j * 16] = (float)acc[i][j];
        }
    }
}

// ============================================================================
// Launch (3 launches per call -> ncu -s5 lands on the GEMM)
// ============================================================================
extern "C" void kernel_launch(void* const* d_in, const int* in_sizes, int n_in,
                              void* d_out, int out_size)
{
    const float* x = (const float*)d_in[0];
    const float* w = (const float*)d_in[1];
    float* out = (float*)d_out;

    prep_q_kernel<<<(N16_TOTAL + 255) / 256, 256>>>(x, w);
    prep_pk_kernel<<<(PK_TOTAL + 255) / 256, 256>>>(x, w);

    static bool attr_set = false;
    if (!attr_set) {
        cudaFuncSetAttribute(ternary_gemm_kernel,
                             cudaFuncAttributeMaxDynamicSharedMemorySize, SMEM_TOTAL);
        attr_set = true;
    }
    ternary_gemm_kernel<<<TOTAL_CTAS, THREADS, SMEM_TOTAL>>>(out);
}